// round 1
// baseline (speedup 1.0000x reference)
#include <cuda_runtime.h>
#include <math.h>

#define H 256
#define S 8   // samples per block

// Dynamic shared memory layout:
//   float4 sa[S][H]  : {h, g0, g1, g2}
//   float4 sb[S][H]  : {s0, s1, s2, pad}
//   float  red[S][8][8] : cross-warp reduction scratch
#define SMEM_BYTES (2 * S * H * 16 + S * 8 * 8 * 4)

__device__ __forceinline__ float my_tanhf(float z) {
    // accurate-enough tanh regardless of fast-math flags:
    // tanh(|z|) = (1 - e^{-2|z|}) / (1 + e^{-2|z|})
    float a = fabsf(z);
    float e = __expf(-2.0f * a);
    float t = __fdividef(1.0f - e, 1.0f + e);
    return copysignf(t, z);
}

__global__ __launch_bounds__(256, 2) void pinn_jet_kernel(
    const float* __restrict__ x,
    const float* __restrict__ W0, const float* __restrict__ b0,
    const float* __restrict__ W1, const float* __restrict__ b1,
    const float* __restrict__ W2, const float* __restrict__ b2,
    const float* __restrict__ W3, const float* __restrict__ b3,
    const float* __restrict__ Wout, const float* __restrict__ bout,
    float* __restrict__ out, int B)
{
    extern __shared__ float smem_raw[];
    float4* sa  = (float4*)smem_raw;          // [S][H]
    float4* sb  = sa + S * H;                 // [S][H]
    float*  red = (float*)(sb + S * H);       // [S][8][8]

    const int j    = threadIdx.x;
    const int base = blockIdx.x * S;

    // ---------------- layer 0: x[3] -> h[256] with analytic jets ----------
    const float w0x = W0[j];
    const float w0y = W0[H + j];
    const float w0z = W0[2 * H + j];
    const float bj0 = b0[j];

    #pragma unroll
    for (int s = 0; s < S; s++) {
        int idx = base + s; if (idx >= B) idx = B - 1;
        float xs0 = __ldg(&x[idx * 3 + 0]);
        float xs1 = __ldg(&x[idx * 3 + 1]);
        float xs2 = __ldg(&x[idx * 3 + 2]);
        float z = fmaf(xs2, w0z, fmaf(xs1, w0y, fmaf(xs0, w0x, bj0)));
        float h = my_tanhf(z);
        float t = 1.0f - h * h;
        float c = -2.0f * h * t;
        // dz/dx_i = W0[i,j]; d2z/dx_i2 = 0
        sa[s * H + j] = make_float4(h, t * w0x, t * w0y, t * w0z);
        sb[s * H + j] = make_float4(c * w0x * w0x, c * w0y * w0y, c * w0z * w0z, 0.0f);
    }
    __syncthreads();

    // ---------------- hidden layers 1..3 ----------------------------------
    const float* Ws[3] = {W1, W2, W3};
    const float* bs[3] = {b1, b2, b3};

    #pragma unroll 1
    for (int l = 0; l < 3; l++) {
        const float* __restrict__ W = Ws[l];
        const float bl = __ldg(&bs[l][j]);

        float zh[S], zg0[S], zg1[S], zg2[S], zs0[S], zs1[S], zs2[S];
        #pragma unroll
        for (int s = 0; s < S; s++) {
            zh[s] = bl; zg0[s] = 0.f; zg1[s] = 0.f; zg2[s] = 0.f;
            zs0[s] = 0.f; zs1[s] = 0.f; zs2[s] = 0.f;
        }

        // z = h @ W ; z' = g @ W ; z'' = s @ W   (weight column j per thread)
        float w = __ldg(&W[j]);
        for (int k = 0; k < H; k++) {
            float wn = (k + 1 < H) ? __ldg(&W[(k + 1) * H + j]) : 0.0f;
            #pragma unroll
            for (int s = 0; s < S; s++) {
                float4 a = sa[s * H + k];   // broadcast LDS.128
                float4 b = sb[s * H + k];   // broadcast LDS.128
                zh [s] = fmaf(w, a.x, zh [s]);
                zg0[s] = fmaf(w, a.y, zg0[s]);
                zg1[s] = fmaf(w, a.z, zg1[s]);
                zg2[s] = fmaf(w, a.w, zg2[s]);
                zs0[s] = fmaf(w, b.x, zs0[s]);
                zs1[s] = fmaf(w, b.y, zs1[s]);
                zs2[s] = fmaf(w, b.z, zs2[s]);
            }
            w = wn;
        }
        __syncthreads();

        #pragma unroll
        for (int s = 0; s < S; s++) {
            float h = my_tanhf(zh[s]);
            float t = 1.0f - h * h;
            float c = -2.0f * h * t;
            sa[s * H + j] = make_float4(h, t * zg0[s], t * zg1[s], t * zg2[s]);
            sb[s * H + j] = make_float4(fmaf(c * zg0[s], zg0[s], t * zs0[s]),
                                        fmaf(c * zg1[s], zg1[s], t * zs1[s]),
                                        fmaf(c * zg2[s], zg2[s], t * zs2[s]),
                                        0.0f);
        }
        __syncthreads();
    }

    // ---------------- output layer: scalar head, 7 reductions -------------
    const float wj   = __ldg(&Wout[j]);
    const int   lane = j & 31;
    const int   warp = j >> 5;

    #pragma unroll
    for (int s = 0; s < S; s++) {
        float4 a = sa[s * H + j];
        float4 b = sb[s * H + j];
        float p0 = a.x * wj, p1 = a.y * wj, p2 = a.z * wj, p3 = a.w * wj;
        float p4 = b.x * wj, p5 = b.y * wj, p6 = b.z * wj;
        #pragma unroll
        for (int off = 16; off > 0; off >>= 1) {
            p0 += __shfl_down_sync(0xffffffffu, p0, off);
            p1 += __shfl_down_sync(0xffffffffu, p1, off);
            p2 += __shfl_down_sync(0xffffffffu, p2, off);
            p3 += __shfl_down_sync(0xffffffffu, p3, off);
            p4 += __shfl_down_sync(0xffffffffu, p4, off);
            p5 += __shfl_down_sync(0xffffffffu, p5, off);
            p6 += __shfl_down_sync(0xffffffffu, p6, off);
        }
        if (lane == 0) {
            float* r = red + (s * 8 + warp) * 8;
            r[0] = p0; r[1] = p1; r[2] = p2; r[3] = p3;
            r[4] = p4; r[5] = p5; r[6] = p6;
        }
    }
    __syncthreads();

    if (j < S * 7) {
        int s = j / 7, c = j % 7;
        int idx = base + s;
        if (idx < B) {
            float v = 0.0f;
            #pragma unroll
            for (int wg = 0; wg < 8; wg++) v += red[(s * 8 + wg) * 8 + c];
            if (c == 0) v += __ldg(&bout[0]);
            out[idx * 7 + c] = v;
        }
    }
}

extern "C" void kernel_launch(void* const* d_in, const int* in_sizes, int n_in,
                              void* d_out, int out_size)
{
    const float* x    = (const float*)d_in[0];
    const float* W0   = (const float*)d_in[1];
    const float* b0   = (const float*)d_in[2];
    const float* W1   = (const float*)d_in[3];
    const float* b1   = (const float*)d_in[4];
    const float* W2   = (const float*)d_in[5];
    const float* b2   = (const float*)d_in[6];
    const float* W3   = (const float*)d_in[7];
    const float* b3   = (const float*)d_in[8];
    const float* Wout = (const float*)d_in[9];
    const float* bout = (const float*)d_in[10];
    float* out = (float*)d_out;

    const int B = in_sizes[0] / 3;
    const int nblk = (B + S - 1) / S;

    cudaFuncSetAttribute(pinn_jet_kernel,
                         cudaFuncAttributeMaxDynamicSharedMemorySize, SMEM_BYTES);
    pinn_jet_kernel<<<nblk, 256, SMEM_BYTES>>>(x, W0, b0, W1, b1, W2, b2, W3, b3,
                                               Wout, bout, out, B);
}

// round 2
// speedup vs baseline: 1.5445x; 1.5445x over previous
#include <cuda_runtime.h>
#include <math.h>

#define H   256
#define S   8     // samples per block
#define TPB 128   // each thread owns columns j and j+128

// Dynamic shared memory layout:
//   ulonglong2 sa2[S][H] : packed {h,g0 | g1,g2}
//   ulonglong2 sb2[S][H] : packed {s0,s1 | s2,0}
//   float      red[S][4][8]
#define SMEM_BYTES (2 * S * H * 16 + S * 4 * 8 * 4)

typedef unsigned long long u64;

__device__ __forceinline__ u64 pack2(float lo, float hi) {
    u64 r; asm("mov.b64 %0,{%1,%2};" : "=l"(r) : "f"(lo), "f"(hi)); return r;
}
__device__ __forceinline__ void unpack2(u64 v, float& lo, float& hi) {
    asm("mov.b64 {%0,%1},%2;" : "=f"(lo), "=f"(hi) : "l"(v));
}
__device__ __forceinline__ u64 fma2(u64 a, u64 b, u64 c) {
    u64 d; asm("fma.rn.f32x2 %0,%1,%2,%3;" : "=l"(d) : "l"(a), "l"(b), "l"(c)); return d;
}

__device__ __forceinline__ float my_tanhf(float z) {
    float a = fabsf(z);
    float e = __expf(-2.0f * a);
    float t = __fdividef(1.0f - e, 1.0f + e);
    return copysignf(t, z);
}

// z-jets -> activation jets: out = {h, t*g0, t*g1, t*g2, s0', s1', s2'}
__device__ __forceinline__ void act_jets(u64 z01, u64 z23, u64 z45, u64 z6p, float out[7]) {
    float zh, zg0, zg1, zg2, zs0, zs1, zs2, dummy;
    unpack2(z01, zh, zg0); unpack2(z23, zg1, zg2);
    unpack2(z45, zs0, zs1); unpack2(z6p, zs2, dummy);
    float h = my_tanhf(zh);
    float t = 1.0f - h * h;
    float c = -2.0f * h * t;
    out[0] = h;
    out[1] = t * zg0; out[2] = t * zg1; out[3] = t * zg2;
    out[4] = fmaf(c * zg0, zg0, t * zs0);
    out[5] = fmaf(c * zg1, zg1, t * zs1);
    out[6] = fmaf(c * zg2, zg2, t * zs2);
}

__global__ __launch_bounds__(TPB, 2) void pinn_jet2_kernel(
    const float* __restrict__ x,
    const float* __restrict__ W0, const float* __restrict__ b0,
    const float* __restrict__ W1, const float* __restrict__ b1,
    const float* __restrict__ W2, const float* __restrict__ b2,
    const float* __restrict__ W3, const float* __restrict__ b3,
    const float* __restrict__ Wout, const float* __restrict__ bout,
    float* __restrict__ out, int B)
{
    extern __shared__ float smem_raw[];
    ulonglong2* sa2 = (ulonglong2*)smem_raw;   // [S][H]
    ulonglong2* sb2 = sa2 + S * H;             // [S][H]
    float*      red = (float*)(sb2 + S * H);   // [S][4][8]

    const int j    = threadIdx.x;        // column A
    const int j2   = j + TPB;            // column B
    const int base = blockIdx.x * S;

    // ---------------- layer 0: x[3] -> jets for cols j and j2 -------------
    {
        const float wax = W0[j],       way = W0[H + j],   waz = W0[2 * H + j];
        const float wbx = W0[j2],      wby = W0[H + j2],  wbz = W0[2 * H + j2];
        const float ba  = b0[j],       bb  = b0[j2];
        #pragma unroll
        for (int s = 0; s < S; s++) {
            int idx = base + s; if (idx >= B) idx = B - 1;
            float x0 = __ldg(&x[idx * 3 + 0]);
            float x1 = __ldg(&x[idx * 3 + 1]);
            float x2 = __ldg(&x[idx * 3 + 2]);
            // column A
            float z = fmaf(x2, waz, fmaf(x1, way, fmaf(x0, wax, ba)));
            float h = my_tanhf(z), t = 1.0f - h * h, c = -2.0f * h * t;
            sa2[s * H + j]  = make_ulonglong2(pack2(h, t * wax), pack2(t * way, t * waz));
            sb2[s * H + j]  = make_ulonglong2(pack2(c * wax * wax, c * way * way),
                                              pack2(c * waz * waz, 0.0f));
            // column B
            z = fmaf(x2, wbz, fmaf(x1, wby, fmaf(x0, wbx, bb)));
            h = my_tanhf(z); t = 1.0f - h * h; c = -2.0f * h * t;
            sa2[s * H + j2] = make_ulonglong2(pack2(h, t * wbx), pack2(t * wby, t * wbz));
            sb2[s * H + j2] = make_ulonglong2(pack2(c * wbx * wbx, c * wby * wby),
                                              pack2(c * wbz * wbz, 0.0f));
        }
    }
    __syncthreads();

    // ---------------- hidden layers 1..3 ----------------------------------
    const float* Ws[3] = {W1, W2, W3};
    const float* bs[3] = {b1, b2, b3};

    #pragma unroll 1
    for (int l = 0; l < 3; l++) {
        const float* __restrict__ W = Ws[l];
        const float bla = __ldg(&bs[l][j]);
        const float blb = __ldg(&bs[l][j2]);

        // z-jet accumulators: 4 packed pairs per (sample, column)
        u64 a0[S], a1[S], a2[S], a3[S];     // column A
        u64 c0[S], c1[S], c2[S], c3[S];     // column B
        #pragma unroll
        for (int s = 0; s < S; s++) {
            a0[s] = pack2(bla, 0.0f); a1[s] = 0ull; a2[s] = 0ull; a3[s] = 0ull;
            c0[s] = pack2(blb, 0.0f); c1[s] = 0ull; c2[s] = 0ull; c3[s] = 0ull;
        }

        float wa = __ldg(&W[j]);
        float wb = __ldg(&W[j2]);
        for (int k = 0; k < H; k++) {
            float wan = (k + 1 < H) ? __ldg(&W[(k + 1) * H + j])  : 0.0f;
            float wbn = (k + 1 < H) ? __ldg(&W[(k + 1) * H + j2]) : 0.0f;
            u64 wa2 = pack2(wa, wa);
            u64 wb2 = pack2(wb, wb);
            #pragma unroll
            for (int s = 0; s < S; s++) {
                ulonglong2 A  = sa2[s * H + k];   // broadcast LDS.128
                ulonglong2 Bv = sb2[s * H + k];   // broadcast LDS.128
                a0[s] = fma2(wa2, A.x,  a0[s]);
                a1[s] = fma2(wa2, A.y,  a1[s]);
                a2[s] = fma2(wa2, Bv.x, a2[s]);
                a3[s] = fma2(wa2, Bv.y, a3[s]);
                c0[s] = fma2(wb2, A.x,  c0[s]);
                c1[s] = fma2(wb2, A.y,  c1[s]);
                c2[s] = fma2(wb2, Bv.x, c2[s]);
                c3[s] = fma2(wb2, Bv.y, c3[s]);
            }
            wa = wan; wb = wbn;
        }

        if (l < 2) {
            __syncthreads();
            #pragma unroll
            for (int s = 0; s < S; s++) {
                float fa[7], fb[7];
                act_jets(a0[s], a1[s], a2[s], a3[s], fa);
                act_jets(c0[s], c1[s], c2[s], c3[s], fb);
                sa2[s * H + j]  = make_ulonglong2(pack2(fa[0], fa[1]), pack2(fa[2], fa[3]));
                sb2[s * H + j]  = make_ulonglong2(pack2(fa[4], fa[5]), pack2(fa[6], 0.0f));
                sa2[s * H + j2] = make_ulonglong2(pack2(fb[0], fb[1]), pack2(fb[2], fb[3]));
                sb2[s * H + j2] = make_ulonglong2(pack2(fb[4], fb[5]), pack2(fb[6], 0.0f));
            }
            __syncthreads();
        } else {
            // ---------------- output head fused into last layer -----------
            const float woa = __ldg(&Wout[j]);
            const float wob = __ldg(&Wout[j2]);
            const int lane  = j & 31;
            const int warp  = j >> 5;

            #pragma unroll
            for (int s = 0; s < S; s++) {
                float fa[7], fb[7], p[7];
                act_jets(a0[s], a1[s], a2[s], a3[s], fa);
                act_jets(c0[s], c1[s], c2[s], c3[s], fb);
                #pragma unroll
                for (int c = 0; c < 7; c++) p[c] = fmaf(fa[c], woa, fb[c] * wob);
                #pragma unroll
                for (int off = 16; off > 0; off >>= 1) {
                    #pragma unroll
                    for (int c = 0; c < 7; c++)
                        p[c] += __shfl_down_sync(0xffffffffu, p[c], off);
                }
                if (lane == 0) {
                    float* r = red + (s * 4 + warp) * 8;
                    #pragma unroll
                    for (int c = 0; c < 7; c++) r[c] = p[c];
                }
            }
            __syncthreads();

            if (j < S * 7) {
                int s = j / 7, c = j % 7;
                int idx = base + s;
                if (idx < B) {
                    float v = red[(s * 4 + 0) * 8 + c] + red[(s * 4 + 1) * 8 + c]
                            + red[(s * 4 + 2) * 8 + c] + red[(s * 4 + 3) * 8 + c];
                    if (c == 0) v += __ldg(&bout[0]);
                    out[idx * 7 + c] = v;
                }
            }
        }
    }
}

extern "C" void kernel_launch(void* const* d_in, const int* in_sizes, int n_in,
                              void* d_out, int out_size)
{
    const float* x    = (const float*)d_in[0];
    const float* W0   = (const float*)d_in[1];
    const float* b0   = (const float*)d_in[2];
    const float* W1   = (const float*)d_in[3];
    const float* b1   = (const float*)d_in[4];
    const float* W2   = (const float*)d_in[5];
    const float* b2   = (const float*)d_in[6];
    const float* W3   = (const float*)d_in[7];
    const float* b3   = (const float*)d_in[8];
    const float* Wout = (const float*)d_in[9];
    const float* bout = (const float*)d_in[10];
    float* out = (float*)d_out;

    const int B = in_sizes[0] / 3;
    const int nblk = (B + S - 1) / S;

    cudaFuncSetAttribute(pinn_jet2_kernel,
                         cudaFuncAttributeMaxDynamicSharedMemorySize, SMEM_BYTES);
    pinn_jet2_kernel<<<nblk, TPB, SMEM_BYTES>>>(x, W0, b0, W1, b1, W2, b2, W3, b3,
                                                Wout, bout, out, B);
}